// round 3
// baseline (speedup 1.0000x reference)
#include <cuda_runtime.h>
#include <math_constants.h>

#define DIMD 256
#define NTOK 4096
#define BATCH 4
#define ROWS_TOTAL (BATCH * NTOK)
#define ATT_SCALE 0.17677669529663687f
#define THRESH 0.6f
#define APITCH 256   // duplicated A tile row: 128 rows -> 256 floats
#define BPITCH 128

typedef unsigned long long ull;

// ---------------- scratch (device globals; no allocation allowed) -------------
__device__ float g_q[ROWS_TOTAL * DIMD];
__device__ float g_k[ROWS_TOTAL * DIMD];
__device__ float g_z[ROWS_TOTAL * DIMD];
__device__ float g_M[DIMD * DIMD];
__device__ float g_pm[2 * ROWS_TOTAL];
__device__ float g_ps[2 * ROWS_TOTAL];
__device__ int   g_pj[2 * ROWS_TOTAL];

// ---------------- f32x2 helpers ----------------------------------------------
__device__ __forceinline__ void fma2(ull &d, ull a, ull b) {
    asm("fma.rn.f32x2 %0, %1, %2, %0;" : "+l"(d) : "l"(a), "l"(b));
}
__device__ __forceinline__ float2 unpack2(ull v) {
    unsigned lo, hi;
    asm("mov.b64 {%0, %1}, %2;" : "=r"(lo), "=r"(hi) : "l"(v));
    return make_float2(__uint_as_float(lo), __uint_as_float(hi));
}

// Load 128 rows x 32 k-cols chunk TRANSPOSED + DUPLICATED:
// dst[k][2*row] = dst[k][2*row+1] = src[row][k]
__device__ __forceinline__ void load_tile_T_dup(float (*dst)[APITCH], const float* __restrict__ src, int tid) {
#pragma unroll
    for (int l = 0; l < 4; l++) {
        int idx = tid + l * 256;
        int row = idx >> 3;
        int k4  = idx & 7;
        float4 v = *(const float4*)(src + row * DIMD + k4 * 4);
        float2* d;
        d = (float2*)&dst[k4 * 4 + 0][2 * row]; *d = make_float2(v.x, v.x);
        d = (float2*)&dst[k4 * 4 + 1][2 * row]; *d = make_float2(v.y, v.y);
        d = (float2*)&dst[k4 * 4 + 2][2 * row]; *d = make_float2(v.z, v.z);
        d = (float2*)&dst[k4 * 4 + 3][2 * row]; *d = make_float2(v.w, v.w);
    }
}

// Load 128 rows x 32 k-cols chunk TRANSPOSED (natural) into dst[32][BPITCH]
__device__ __forceinline__ void load_tile_T(float (*dst)[BPITCH], const float* __restrict__ src, int tid) {
#pragma unroll
    for (int l = 0; l < 4; l++) {
        int idx = tid + l * 256;
        int row = idx >> 3;
        int k4  = idx & 7;
        float4 v = *(const float4*)(src + row * DIMD + k4 * 4);
        dst[k4 * 4 + 0][row] = v.x;
        dst[k4 * 4 + 1][row] = v.y;
        dst[k4 * 4 + 2][row] = v.z;
        dst[k4 * 4 + 3][row] = v.w;
    }
}

// Load 32 k-rows x 128 cols chunk NATURAL into dst[32][BPITCH]
__device__ __forceinline__ void load_tile_N(float (*dst)[BPITCH], const float* __restrict__ src, int tid) {
#pragma unroll
    for (int l = 0; l < 4; l++) {
        int idx = tid + l * 256;
        int k  = idx >> 5;
        int c4 = idx & 31;
        float4 v = *(const float4*)(src + k * DIMD + c4 * 4);
        *(float4*)&dst[k][c4 * 4] = v;
    }
}

// one K-step of the 128x128 (8x8 per-thread) f32x2 micro-kernel, dup-A layout
__device__ __forceinline__ void mma_step(const float (*as_)[APITCH], const float (*bs_)[BPITCH],
                                         int k, int tx, int ty, ull acc[8][4]) {
    const ulonglong2* bp2 = (const ulonglong2*)&bs_[k][tx * 8];
    ulonglong2 b01 = bp2[0], b23 = bp2[1];
    ull B[4] = { b01.x, b01.y, b23.x, b23.y };

    const ulonglong2* ap2 = (const ulonglong2*)&as_[k][ty * 16];
    ulonglong2 a0 = ap2[0], a1 = ap2[1], a2 = ap2[2], a3 = ap2[3];
    ull A[8] = { a0.x, a0.y, a1.x, a1.y, a2.x, a2.y, a3.x, a3.y };
#pragma unroll
    for (int r = 0; r < 8; r++)
#pragma unroll
        for (int c = 0; c < 4; c++)
            fma2(acc[r][c], A[r], B[c]);
}

// ---------------- generic tiled GEMM: C[M x 256] = A[M x 256] @ B[256 x 256] (+bias)
__global__ __launch_bounds__(256, 2) void gemm_kernel(const float* __restrict__ A,
                                                      const float* __restrict__ B,
                                                      float* __restrict__ C,
                                                      const float* __restrict__ bias,
                                                      int hasBias) {
    __shared__ __align__(16) float as_[32][APITCH];
    __shared__ __align__(16) float bs_[32][BPITCH];
    int tid = threadIdx.x, tx = tid & 15, ty = tid >> 4;
    int rb = blockIdx.x * 128, cb = blockIdx.y * 128;

    ull acc[8][4];
#pragma unroll
    for (int r = 0; r < 8; r++)
#pragma unroll
        for (int c = 0; c < 4; c++) acc[r][c] = 0ULL;

    for (int kk = 0; kk < DIMD; kk += 32) {
        load_tile_T_dup(as_, A + (size_t)rb * DIMD + kk, tid);
        load_tile_N(bs_, B + (size_t)kk * DIMD + cb, tid);
        __syncthreads();
#pragma unroll 8
        for (int k = 0; k < 32; k++) mma_step(as_, bs_, k, tx, ty, acc);
        __syncthreads();
    }

    float bv[8];
    if (hasBias) {
        float4 b0 = *(const float4*)(bias + cb + tx * 8);
        float4 b1 = *(const float4*)(bias + cb + tx * 8 + 4);
        bv[0] = b0.x; bv[1] = b0.y; bv[2] = b0.z; bv[3] = b0.w;
        bv[4] = b1.x; bv[5] = b1.y; bv[6] = b1.z; bv[7] = b1.w;
    } else {
#pragma unroll
        for (int i = 0; i < 8; i++) bv[i] = 0.f;
    }

#pragma unroll
    for (int r = 0; r < 8; r++) {
        float v[8];
#pragma unroll
        for (int c = 0; c < 4; c++) {
            float2 u = unpack2(acc[r][c]);
            v[2 * c]     = u.x + bv[2 * c];
            v[2 * c + 1] = u.y + bv[2 * c + 1];
        }
        int row = rb + ty * 8 + r;
        float* dst = C + (size_t)row * DIMD + cb + tx * 8;
        *(float4*)dst       = make_float4(v[0], v[1], v[2], v[3]);
        *(float4*)(dst + 4) = make_float4(v[4], v[5], v[6], v[7]);
    }
}

// ---------------- streaming attention stats over half of the key range -------
// grid (NTOK/128, BATCH, 2); each CTA produces partial (m, s, argmax) per row
__global__ __launch_bounds__(256, 2) void attn_kernel() {
    __shared__ __align__(16) float qs_[32][APITCH];
    __shared__ __align__(16) float ks_[32][BPITCH];
    int tid = threadIdx.x, tx = tid & 15, ty = tid >> 4;
    int b = blockIdx.y;
    int rb = blockIdx.x * 128;
    int half = blockIdx.z;

    const float* qbase  = g_q + ((size_t)b * NTOK + rb) * DIMD;
    const float* kbase0 = g_k + ((size_t)b * NTOK + (size_t)half * (NTOK / 2)) * DIMD;

    float m[8], s[8];
    int ja[8];
#pragma unroll
    for (int r = 0; r < 8; r++) { m[r] = -CUDART_INF_F; s[r] = 0.f; ja[r] = 0; }

    for (int jt = 0; jt < NTOK / 256; jt++) {   // 16 tiles of 128 cols per half
        ull acc[8][4];
#pragma unroll
        for (int r = 0; r < 8; r++)
#pragma unroll
            for (int c = 0; c < 4; c++) acc[r][c] = 0ULL;

        const float* kbase = kbase0 + (size_t)jt * 128 * DIMD;
        for (int kk = 0; kk < DIMD; kk += 32) {
            load_tile_T_dup(qs_, qbase + kk, tid);
            load_tile_T(ks_, kbase + kk, tid);
            __syncthreads();
#pragma unroll 8
            for (int k = 0; k < 32; k++) mma_step(qs_, ks_, k, tx, ty, acc);
            __syncthreads();
        }

        int colbase = half * (NTOK / 2) + jt * 128 + tx * 8;
#pragma unroll
        for (int r = 0; r < 8; r++) {
            float l[8];
#pragma unroll
            for (int c = 0; c < 4; c++) {
                float2 u = unpack2(acc[r][c]);
                l[2 * c]     = u.x * ATT_SCALE;
                l[2 * c + 1] = u.y * ATT_SCALE;
            }
            float tmax = l[0];
            int   targ = colbase;
#pragma unroll
            for (int c = 1; c < 8; c++)
                if (l[c] > tmax) { tmax = l[c]; targ = colbase + c; }
#pragma unroll
            for (int o = 1; o < 16; o <<= 1) {
                float om = __shfl_xor_sync(0xffffffffu, tmax, o);
                int   oa = __shfl_xor_sync(0xffffffffu, targ, o);
                if (om > tmax) { tmax = om; targ = oa; }
            }
            float nm = fmaxf(m[r], tmax);
            float tsum = 0.f;
#pragma unroll
            for (int c = 0; c < 8; c++) tsum += __expf(l[c] - nm);
#pragma unroll
            for (int o = 1; o < 16; o <<= 1)
                tsum += __shfl_xor_sync(0xffffffffu, tsum, o);
            s[r] = s[r] * __expf(m[r] - nm) + tsum;
            if (tmax > m[r]) ja[r] = targ;
            m[r] = nm;
        }
    }

    if (tx == 0) {
#pragma unroll
        for (int r = 0; r < 8; r++) {
            int row = b * NTOK + rb + ty * 8 + r;
            int pr  = half * ROWS_TOTAL + row;
            g_pm[pr] = m[r];
            g_ps[pr] = s[r];
            g_pj[pr] = ja[r];
        }
    }
}

// ---------------- combine partials + build Z: spike rows p * x[argmax] -------
__global__ __launch_bounds__(256) void zbuild_kernel(const float* __restrict__ x) {
    int row = blockIdx.x;
    int b = row >> 12;                 // NTOK = 4096
    float m0 = g_pm[row],              m1 = g_pm[ROWS_TOTAL + row];
    float s0 = g_ps[row],              s1 = g_ps[ROWS_TOTAL + row];
    float mm = fmaxf(m0, m1);
    float s  = s0 * __expf(m0 - mm) + s1 * __expf(m1 - mm);
    float p  = 1.0f / s;               // p_max = exp(m - lse) = 1/sumexp
    int   j  = (m0 >= m1) ? g_pj[row] : g_pj[ROWS_TOTAL + row];

    int tid = threadIdx.x;
    float v = 0.f;
    if (p >= THRESH) {
        const float* src = x + ((size_t)((b << 12) + j)) * DIMD;
        v = p * src[tid];
    }
    g_z[(size_t)row * DIMD + tid] = v;
}

// -----------------------------------------------------------------------------
extern "C" void kernel_launch(void* const* d_in, const int* in_sizes, int n_in,
                              void* d_out, int out_size) {
    (void)in_sizes; (void)n_in; (void)out_size;
    const float* x  = (const float*)d_in[0];
    const float* y  = (const float*)d_in[1];
    const float* Wq = (const float*)d_in[2];
    const float* Wk = (const float*)d_in[3];
    const float* Wv = (const float*)d_in[4];
    const float* Wp = (const float*)d_in[5];
    const float* bp = (const float*)d_in[6];
    float* out = (float*)d_out;

    float *q, *k, *z, *M;
    cudaGetSymbolAddress((void**)&q, g_q);
    cudaGetSymbolAddress((void**)&k, g_k);
    cudaGetSymbolAddress((void**)&z, g_z);
    cudaGetSymbolAddress((void**)&M, g_M);

    dim3 blk(256);
    // projections
    gemm_kernel<<<dim3(ROWS_TOTAL / 128, 2), blk>>>(x, Wq, q, nullptr, 0);
    gemm_kernel<<<dim3(ROWS_TOTAL / 128, 2), blk>>>(y, Wk, k, nullptr, 0);
    // fused projection matrix M = Wv @ Wp
    gemm_kernel<<<dim3(2, 2), blk>>>(Wv, Wp, M, nullptr, 0);
    // streaming softmax stats (max/argmax/sumexp), key range split in halves
    attn_kernel<<<dim3(NTOK / 128, BATCH, 2), blk>>>();
    // combine halves + sparse spike rows
    zbuild_kernel<<<ROWS_TOTAL, blk>>>(x);
    // out = Z @ M + bp
    gemm_kernel<<<dim3(ROWS_TOTAL / 128, 2), blk>>>(z, M, out, bp, 1);
}

// round 4
// speedup vs baseline: 1.1483x; 1.1483x over previous
#include <cuda_runtime.h>
#include <math_constants.h>

#define DIMD 256
#define NTOK 4096
#define BATCH 4
#define ROWS_TOTAL (BATCH * NTOK)
#define ATT_SCALE 0.17677669529663687f
#define THRESH 0.6f

typedef unsigned long long ull;

// ---------------- scratch (device globals; no allocation allowed) -------------
__device__ float g_q[ROWS_TOTAL * DIMD];
__device__ float g_k[ROWS_TOTAL * DIMD];
__device__ float g_z[ROWS_TOTAL * DIMD];
__device__ float g_M[DIMD * DIMD];
__device__ float g_p[ROWS_TOTAL];
__device__ int   g_j[ROWS_TOTAL];

// ---------------- f32x2 helpers ----------------------------------------------
__device__ __forceinline__ void fma2(ull &d, ull a, ull b) {
    asm("fma.rn.f32x2 %0, %1, %2, %0;" : "+l"(d) : "l"(a), "l"(b));
}
__device__ __forceinline__ float2 unpack2(ull v) {
    unsigned lo, hi;
    asm("mov.b64 {%0, %1}, %2;" : "=r"(lo), "=r"(hi) : "l"(v));
    return make_float2(__uint_as_float(lo), __uint_as_float(hi));
}

// ============ shared tile layouts ============================================
// A tile (dup): 32 k-rows x 256 floats. Row r (0..127) of chunk-dim k stored as
//   duplicated pair {a,a} at word  k*256 + 2*(r ^ ((k>>2)<<2))
// B tile (pair-swizzle): 32 k-rows x 128 floats. Col c stored at word
//   k*128 + e2*32 + ((tx ^ (k>>2) ^ ((e2&1)<<3))<<1) + o
//   where tx=c>>3, e2=(c>>1)&3, o=c&1.

// ---- global loads (prefetch into regs), T-access pattern: row-major [128 x 256]
__device__ __forceinline__ void ldg_T(float4 v[4], const float* __restrict__ src, int tid) {
#pragma unroll
    for (int l = 0; l < 4; l++) {
        int idx = tid + l * 256, row = idx >> 3, k4 = idx & 7;
        v[l] = *(const float4*)(src + row * DIMD + k4 * 4);
    }
}
// N-access pattern for weight matrices: [32 k-rows x 128 cols] chunk of [256 x 256]
__device__ __forceinline__ void ldg_N(float4 v[4], const float* __restrict__ src, int tid) {
#pragma unroll
    for (int l = 0; l < 4; l++) {
        int idx = tid + l * 256, kr = idx >> 5, c4 = idx & 31;
        v[l] = *(const float4*)(src + kr * DIMD + c4 * 4);
    }
}

// ---- stores: regs -> smem
// A dup store: thread holds (row, k4) with 4 consecutive dims k=4*k4+i
__device__ __forceinline__ void sts_A_dup(float* dst, const float4 v[4], int tid) {
#pragma unroll
    for (int l = 0; l < 4; l++) {
        int idx = tid + l * 256, row = idx >> 3, k4 = idx & 7;
        int pos = row ^ (k4 << 2);                 // k>>2 == k4 for all i
        float* d = dst + (4 * k4) * 256 + 2 * pos;
        *(float2*)(d          ) = make_float2(v[l].x, v[l].x);
        *(float2*)(d + 256    ) = make_float2(v[l].y, v[l].y);
        *(float2*)(d + 512    ) = make_float2(v[l].z, v[l].z);
        *(float2*)(d + 768    ) = make_float2(v[l].w, v[l].w);
    }
}
// B pair-swizzle store from T-pattern regs (key matrix: row index IS the col c)
__device__ __forceinline__ void sts_B_fromT(float* dst, const float4 v[4], int tid) {
#pragma unroll
    for (int l = 0; l < 4; l++) {
        int idx = tid + l * 256, c = idx >> 3, k4 = idx & 7;
        int e2 = (c >> 1) & 3, o = c & 1, txc = c >> 3;
        int w = (e2 << 5) + o + (((txc ^ k4) ^ ((e2 & 1) << 3)) << 1);
        float* d = dst + (4 * k4) * 128 + w;
        d[0]   = v[l].x;
        d[128] = v[l].y;
        d[256] = v[l].z;
        d[384] = v[l].w;
    }
}
// B pair-swizzle store from N-pattern regs (weight matrix: 4 consecutive cols, one k)
__device__ __forceinline__ void sts_B_fromN(float* dst, const float4 v[4], int tid) {
#pragma unroll
    for (int l = 0; l < 4; l++) {
        int idx = tid + l * 256, kr = idx >> 5, c4 = idx & 31;
        int s = kr >> 2;
        int txc = c4 >> 1;
        int e2a = (2 * c4) & 3;                    // pair (4c4, 4c4+1), e2 even
        int w0 = (e2a << 5) + ((txc ^ s) << 1);
        int w1 = ((e2a + 1) << 5) + (((txc ^ s) ^ 8) << 1);
        float* d = dst + kr * 128;
        *(float2*)(d + w0) = make_float2(v[l].x, v[l].y);
        *(float2*)(d + w1) = make_float2(v[l].z, v[l].w);
    }
}

// ---- one k-step of the 128x128 (8 rows x 8 cols per thread) f32x2 micro-kernel
__device__ __forceinline__ void mma_step(const float* __restrict__ as_,
                                         const float* __restrict__ bs_,
                                         int k, int tx, int ty, ull acc[8][4]) {
    int sK = k >> 2;
    int xb0 = (tx ^ sK) << 1;
    int xb1 = xb0 ^ 16;
    const float* kr = bs_ + k * 128;
    ull B[4];
    B[0] = *(const ull*)(kr +      xb0);
    B[1] = *(const ull*)(kr + 32 + xb1);
    B[2] = *(const ull*)(kr + 64 + xb0);
    B[3] = *(const ull*)(kr + 96 + xb1);

    int g = sK << 2;
    const float* qr = as_ + k * 256;
    ulonglong2 A01 = *(const ulonglong2*)(qr + 2 * ((8 * ty + 0) ^ g));
    ulonglong2 A23 = *(const ulonglong2*)(qr + 2 * ((8 * ty + 2) ^ g));
    ulonglong2 A45 = *(const ulonglong2*)(qr + 2 * ((8 * ty + 4) ^ g));
    ulonglong2 A67 = *(const ulonglong2*)(qr + 2 * ((8 * ty + 6) ^ g));
    ull A[8] = { A01.x, A01.y, A23.x, A23.y, A45.x, A45.y, A67.x, A67.y };
#pragma unroll
    for (int r = 0; r < 8; r++)
#pragma unroll
        for (int c = 0; c < 4; c++)
            fma2(acc[r][c], A[r], B[c]);
}

// ---------------- tiled GEMM: C[M x 256] = A[M x 256] @ B[256 x 256] (+bias) --
__global__ __launch_bounds__(256) void gemm_kernel(const float* __restrict__ A,
                                                   const float* __restrict__ B,
                                                   float* __restrict__ C,
                                                   const float* __restrict__ bias,
                                                   int hasBias) {
    __shared__ __align__(16) float as_[32 * 256];
    __shared__ __align__(16) float bs_[32 * 128];
    int tid = threadIdx.x, tx = tid & 15, ty = tid >> 4;
    int rb = blockIdx.x * 128, cb = blockIdx.y * 128;

    ull acc[8][4];
#pragma unroll
    for (int r = 0; r < 8; r++)
#pragma unroll
        for (int c = 0; c < 4; c++) acc[r][c] = 0ULL;

    float4 va[4], vb[4];
    ldg_T(va, A + (size_t)rb * DIMD, tid);
    ldg_N(vb, B + cb, tid);

    for (int ck = 0; ck < 8; ck++) {
        __syncthreads();
        sts_A_dup(as_, va, tid);
        sts_B_fromN(bs_, vb, tid);
        if (ck < 7) {
            int nkk = (ck + 1) * 32;
            ldg_T(va, A + (size_t)rb * DIMD + nkk, tid);
            ldg_N(vb, B + (size_t)nkk * DIMD + cb, tid);
        }
        __syncthreads();
#pragma unroll 8
        for (int k = 0; k < 32; k++) mma_step(as_, bs_, k, tx, ty, acc);
    }

    float bv[8];
    if (hasBias) {
        float4 b0 = *(const float4*)(bias + cb + tx * 8);
        float4 b1 = *(const float4*)(bias + cb + tx * 8 + 4);
        bv[0] = b0.x; bv[1] = b0.y; bv[2] = b0.z; bv[3] = b0.w;
        bv[4] = b1.x; bv[5] = b1.y; bv[6] = b1.z; bv[7] = b1.w;
    } else {
#pragma unroll
        for (int i = 0; i < 8; i++) bv[i] = 0.f;
    }

#pragma unroll
    for (int r = 0; r < 8; r++) {
        float v[8];
#pragma unroll
        for (int c = 0; c < 4; c++) {
            float2 u = unpack2(acc[r][c]);
            v[2 * c]     = u.x + bv[2 * c];
            v[2 * c + 1] = u.y + bv[2 * c + 1];
        }
        int row = rb + ty * 8 + r;
        float* dst = C + (size_t)row * DIMD + cb + tx * 8;
        *(float4*)dst       = make_float4(v[0], v[1], v[2], v[3]);
        *(float4*)(dst + 4) = make_float4(v[4], v[5], v[6], v[7]);
    }
}

// ---------------- streaming attention stats: per row -> (p = 1/sumexp, argmax)
__global__ __launch_bounds__(256) void attn_kernel() {
    __shared__ __align__(16) float qs_[32 * 256];
    __shared__ __align__(16) float ks_[32 * 128];
    int tid = threadIdx.x, tx = tid & 15, ty = tid >> 4;
    int b = blockIdx.y, rb = blockIdx.x * 128;

    const float* qbase  = g_q + ((size_t)b * NTOK + rb) * DIMD;
    const float* kbase0 = g_k + (size_t)b * NTOK * DIMD;

    float m[8], s[8];
    int ja[8];
#pragma unroll
    for (int r = 0; r < 8; r++) { m[r] = -CUDART_INF_F; s[r] = 0.f; ja[r] = 0; }

    float4 vq[4], vk[4];
    ldg_T(vq, qbase, tid);
    ldg_T(vk, kbase0, tid);

    ull acc[8][4];
    const int NIT = (NTOK / 128) * 8;      // 32 key tiles x 8 k-chunks
    for (int it = 0; it < NIT; it++) {
        __syncthreads();
        sts_A_dup(qs_, vq, tid);
        sts_B_fromT(ks_, vk, tid);
        int nit = it + 1;
        if (nit < NIT) {
            int njt = nit >> 3, nkk = (nit & 7) * 32;
            ldg_T(vq, qbase + nkk, tid);
            ldg_T(vk, kbase0 + (size_t)njt * 128 * DIMD + nkk, tid);
        }
        __syncthreads();
        if ((it & 7) == 0) {
#pragma unroll
            for (int r = 0; r < 8; r++)
#pragma unroll
                for (int c = 0; c < 4; c++) acc[r][c] = 0ULL;
        }
#pragma unroll 8
        for (int k = 0; k < 32; k++) mma_step(qs_, ks_, k, tx, ty, acc);

        if ((it & 7) == 7) {
            int jt = it >> 3;
            int colbase = jt * 128 + tx * 8;
#pragma unroll
            for (int r = 0; r < 8; r++) {
                float l[8];
#pragma unroll
                for (int c = 0; c < 4; c++) {
                    float2 u = unpack2(acc[r][c]);
                    l[2 * c]     = u.x * ATT_SCALE;
                    l[2 * c + 1] = u.y * ATT_SCALE;
                }
                float tmax = l[0];
                int   targ = colbase;
#pragma unroll
                for (int c = 1; c < 8; c++)
                    if (l[c] > tmax) { tmax = l[c]; targ = colbase + c; }
#pragma unroll
                for (int o = 1; o < 16; o <<= 1) {
                    float om = __shfl_xor_sync(0xffffffffu, tmax, o);
                    int   oa = __shfl_xor_sync(0xffffffffu, targ, o);
                    if (om > tmax) { tmax = om; targ = oa; }
                }
                float nm = fmaxf(m[r], tmax);
                float tsum = 0.f;
#pragma unroll
                for (int c = 0; c < 8; c++) tsum += __expf(l[c] - nm);
#pragma unroll
                for (int o = 1; o < 16; o <<= 1)
                    tsum += __shfl_xor_sync(0xffffffffu, tsum, o);
                s[r] = s[r] * __expf(m[r] - nm) + tsum;
                if (tmax > m[r]) ja[r] = targ;
                m[r] = nm;
            }
        }
    }

    if (tx == 0) {
#pragma unroll
        for (int r = 0; r < 8; r++) {
            int row = b * NTOK + rb + ty * 8 + r;
            g_p[row] = 1.0f / s[r];    // p_max = exp(m - lse) = 1/sumexp
            g_j[row] = ja[r];
        }
    }
}

// ---------------- build Z: spike rows p * x[argmax], else 0 ------------------
__global__ __launch_bounds__(256) void zbuild_kernel(const float* __restrict__ x) {
    int row = blockIdx.x;
    int b = row >> 12;                 // NTOK = 4096
    float p = g_p[row];
    int tid = threadIdx.x;
    float v = 0.f;
    if (p >= THRESH) {
        const float* src = x + ((size_t)((b << 12) + g_j[row])) * DIMD;
        v = p * src[tid];
    }
    g_z[(size_t)row * DIMD + tid] = v;
}

// -----------------------------------------------------------------------------
extern "C" void kernel_launch(void* const* d_in, const int* in_sizes, int n_in,
                              void* d_out, int out_size) {
    (void)in_sizes; (void)n_in; (void)out_size;
    const float* x  = (const float*)d_in[0];
    const float* y  = (const float*)d_in[1];
    const float* Wq = (const float*)d_in[2];
    const float* Wk = (const float*)d_in[3];
    const float* Wv = (const float*)d_in[4];
    const float* Wp = (const float*)d_in[5];
    const float* bp = (const float*)d_in[6];
    float* out = (float*)d_out;

    float *q, *k, *z, *M;
    cudaGetSymbolAddress((void**)&q, g_q);
    cudaGetSymbolAddress((void**)&k, g_k);
    cudaGetSymbolAddress((void**)&z, g_z);
    cudaGetSymbolAddress((void**)&M, g_M);

    dim3 blk(256);
    // projections
    gemm_kernel<<<dim3(ROWS_TOTAL / 128, 2), blk>>>(x, Wq, q, nullptr, 0);
    gemm_kernel<<<dim3(ROWS_TOTAL / 128, 2), blk>>>(y, Wk, k, nullptr, 0);
    // fused projection matrix M = Wv @ Wp
    gemm_kernel<<<dim3(2, 2), blk>>>(Wv, Wp, M, nullptr, 0);
    // streaming softmax stats (max/argmax/sumexp) over q k^T
    attn_kernel<<<dim3(NTOK / 128, BATCH), blk>>>();
    // sparse spike rows
    zbuild_kernel<<<ROWS_TOTAL, blk>>>(x);
    // out = Z @ M + bp
    gemm_kernel<<<dim3(ROWS_TOTAL / 128, 2), blk>>>(z, M, out, bp, 1);
}